// round 6
// baseline (speedup 1.0000x reference)
#include <cuda_runtime.h>
#include <cstdint>

// IndexedLinearLayer: out[j] = sum_i W[idx[i], i, j] * x[i] + bias[j]
// x f32[8192], indices int32 OR int64 [8192] (dtype detected at runtime),
// param_index f32[16,8192,2048], bias f32[2048] -> out f32[2048]
//
// HBM-streaming gather-GEMV: 64 MiB of gathered weights read exactly once.
// R6: grid 256 -> 512 CTAs (I_PER_BLK 64 -> 32) to double occupancy; the R5
// profile showed occ=20%, issue=7% -> latency-bound, not bandwidth-bound.

#define SIZE_IN    8192
#define SIZE_OUT   2048
#define NUM_Q      16
#define THREADS    256
#define I_PER_BLK  32
#define J_PER_BLK  (THREADS * 4)              // 1024 floats per block
#define J_BLOCKS   (SIZE_OUT / J_PER_BLK)     // 2
#define I_BLOCKS   (SIZE_IN / I_PER_BLK)      // 256

// Decoded indices scratch (no device allocation allowed).
__device__ int g_idx[SIZE_IN];

// Prep: seed out = bias, and decode indices robustly (int32 vs int64).
__global__ __launch_bounds__(THREADS)
void prep_kernel(const void* __restrict__ idx_raw,
                 const float* __restrict__ bias,
                 float* __restrict__ out) {
    __shared__ int s_not64;
    if (threadIdx.x == 0) s_not64 = 0;
    __syncthreads();

    // Probe first 4096 int64-interpreted entries (32 KB: in-bounds for both
    // int32[8192] and int64[8192] buffers). Genuine int64 indices are all in
    // [0,16); int32 data reinterpreted as int64 is out of range w.h.p.
    const long long* p64 = (const long long*)idx_raw;
    int bad = 0;
    for (int k = threadIdx.x; k < SIZE_IN / 2; k += THREADS) {
        long long v = p64[k];
        bad |= (v < 0 || v >= NUM_Q) ? 1 : 0;
    }
    if (bad) s_not64 = 1;       // benign race: all writers store 1
    __syncthreads();

    if (s_not64) {              // int32 indices
        const int* p32 = (const int*)idx_raw;
        for (int k = threadIdx.x; k < SIZE_IN; k += THREADS)
            g_idx[k] = p32[k];
    } else {                    // int64 indices
        for (int k = threadIdx.x; k < SIZE_IN; k += THREADS)
            g_idx[k] = (int)p64[k];
    }

    // Seed output with bias (d_out is poisoned before timing).
    for (int j = threadIdx.x; j < SIZE_OUT; j += THREADS)
        out[j] = bias[j];
}

__global__ __launch_bounds__(THREADS, 4)   // allow up to 64 regs/thread
void indexed_gemv_kernel(const float* __restrict__ x,
                         const float* __restrict__ W,
                         float* __restrict__ out) {
    __shared__ float        s_x[I_PER_BLK];
    __shared__ const float* s_row[I_PER_BLK];

    const int t  = threadIdx.x;
    const int i0 = blockIdx.y * I_PER_BLK;

    // Stage the 32 (x, gathered-row-pointer) pairs for this i-chunk.
    if (t < I_PER_BLK) {
        const int i = i0 + t;
        s_x[t] = x[i];
        const int q = g_idx[i];
        s_row[t] = W + (size_t)q * ((size_t)SIZE_IN * SIZE_OUT)
                     + (size_t)i * SIZE_OUT;
    }
    __syncthreads();

    const int j = blockIdx.x * J_PER_BLK + t * 4;

    float4 acc = make_float4(0.f, 0.f, 0.f, 0.f);

    // Fully-unrolled streaming loop: independent LDG.128s batched in flight.
    #pragma unroll
    for (int k = 0; k < I_PER_BLK; ++k) {
        const float4 w  = *reinterpret_cast<const float4*>(s_row[k] + j);
        const float  xv = s_x[k];
        acc.x = fmaf(w.x, xv, acc.x);
        acc.y = fmaf(w.y, xv, acc.y);
        acc.z = fmaf(w.z, xv, acc.z);
        acc.w = fmaf(w.w, xv, acc.w);
    }

    // Split-K combine: 256 i-blocks fold into each output element (REDG path).
    atomicAdd(&out[j + 0], acc.x);
    atomicAdd(&out[j + 1], acc.y);
    atomicAdd(&out[j + 2], acc.z);
    atomicAdd(&out[j + 3], acc.w);
}

extern "C" void kernel_launch(void* const* d_in, const int* in_sizes, int n_in,
                              void* d_out, int out_size) {
    // Map buffers by size where unique; x/indices keep metadata order.
    const float* x    = (const float*)d_in[0];
    const void*  idxp = d_in[1];
    const float* W    = (const float*)d_in[2];
    const float* bias = (const float*)d_in[3];
    for (int k = 0; k < n_in; ++k) {
        long long sz = in_sizes[k];
        if (sz == (long long)NUM_Q * SIZE_IN * SIZE_OUT) W    = (const float*)d_in[k];
        else if (sz == SIZE_OUT)                         bias = (const float*)d_in[k];
    }
    float* out = (float*)d_out;

    prep_kernel<<<1, THREADS>>>(idxp, bias, out);

    dim3 grid(J_BLOCKS, I_BLOCKS);  // (2, 256) = 512 CTAs
    indexed_gemv_kernel<<<grid, THREADS>>>(x, W, out);
}

// round 7
// speedup vs baseline: 1.4826x; 1.4826x over previous
#include <cuda_runtime.h>
#include <cstdint>

// IndexedLinearLayer: out[j] = sum_i W[idx[i], i, j] * x[i] + bias[j]
// x f32[8192], indices int32 OR int64 [8192] (dtype detected at runtime),
// param_index f32[16,8192,2048], bias f32[2048] -> out f32[2048]
//
// HBM-streaming gather-GEMV: 64 MiB of gathered weights read exactly once.
// R7: keep 512-CTA grid (occupancy win from R6), but collapse the split-K
// combine from 4 scalar atomicAdds to ONE red.global.add.v4.f32 per thread —
// R6 showed the 512K scalar REDs onto 2048 addresses were serializing in the
// LTS atomic ALU and dragging DRAM throughput down.

#define SIZE_IN    8192
#define SIZE_OUT   2048
#define NUM_Q      16
#define THREADS    256
#define I_PER_BLK  32
#define J_PER_BLK  (THREADS * 4)              // 1024 floats per block
#define J_BLOCKS   (SIZE_OUT / J_PER_BLK)     // 2
#define I_BLOCKS   (SIZE_IN / I_PER_BLK)      // 256

// Decoded indices scratch (no device allocation allowed).
__device__ int g_idx[SIZE_IN];

// Prep: seed out = bias, and decode indices robustly (int32 vs int64).
__global__ __launch_bounds__(THREADS)
void prep_kernel(const void* __restrict__ idx_raw,
                 const float* __restrict__ bias,
                 float* __restrict__ out) {
    __shared__ int s_not64;
    if (threadIdx.x == 0) s_not64 = 0;
    __syncthreads();

    // Probe first 4096 int64-interpreted entries (32 KB: in-bounds for both
    // int32[8192] and int64[8192] buffers). Genuine int64 indices are all in
    // [0,16); int32 data reinterpreted as int64 is out of range w.h.p.
    const long long* p64 = (const long long*)idx_raw;
    int bad = 0;
    for (int k = threadIdx.x; k < SIZE_IN / 2; k += THREADS) {
        long long v = p64[k];
        bad |= (v < 0 || v >= NUM_Q) ? 1 : 0;
    }
    if (bad) s_not64 = 1;       // benign race: all writers store 1
    __syncthreads();

    if (s_not64) {              // int32 indices
        const int* p32 = (const int*)idx_raw;
        for (int k = threadIdx.x; k < SIZE_IN; k += THREADS)
            g_idx[k] = p32[k];
    } else {                    // int64 indices
        for (int k = threadIdx.x; k < SIZE_IN; k += THREADS)
            g_idx[k] = (int)p64[k];
    }

    // Seed output with bias (d_out is poisoned before timing).
    for (int j = threadIdx.x; j < SIZE_OUT; j += THREADS)
        out[j] = bias[j];
}

__global__ __launch_bounds__(THREADS, 4)   // up to 64 regs/thread
void indexed_gemv_kernel(const float* __restrict__ x,
                         const float* __restrict__ W,
                         float* __restrict__ out) {
    __shared__ float        s_x[I_PER_BLK];
    __shared__ const float* s_row[I_PER_BLK];

    const int t  = threadIdx.x;
    const int i0 = blockIdx.y * I_PER_BLK;

    // Stage the 32 (x, gathered-row-pointer) pairs for this i-chunk.
    if (t < I_PER_BLK) {
        const int i = i0 + t;
        s_x[t] = x[i];
        const int q = g_idx[i];
        s_row[t] = W + (size_t)q * ((size_t)SIZE_IN * SIZE_OUT)
                     + (size_t)i * SIZE_OUT;
    }
    __syncthreads();

    const int j = blockIdx.x * J_PER_BLK + t * 4;

    float4 acc = make_float4(0.f, 0.f, 0.f, 0.f);

    // Fully-unrolled streaming loop: independent LDG.128s batched in flight.
    #pragma unroll
    for (int k = 0; k < I_PER_BLK; ++k) {
        const float4 w  = *reinterpret_cast<const float4*>(s_row[k] + j);
        const float  xv = s_x[k];
        acc.x = fmaf(w.x, xv, acc.x);
        acc.y = fmaf(w.y, xv, acc.y);
        acc.z = fmaf(w.z, xv, acc.z);
        acc.w = fmaf(w.w, xv, acc.w);
    }

    // Split-K combine: one vectorized no-return reduction per thread.
    // out + j is 16B-aligned (j % 4 == 0). 4x fewer LTS atomic-ALU ops
    // than scalar atomicAdd x4.
    asm volatile("red.global.add.v4.f32 [%0], {%1, %2, %3, %4};"
                 :: "l"(out + j), "f"(acc.x), "f"(acc.y), "f"(acc.z), "f"(acc.w)
                 : "memory");
}

extern "C" void kernel_launch(void* const* d_in, const int* in_sizes, int n_in,
                              void* d_out, int out_size) {
    // Map buffers by size where unique; x/indices keep metadata order.
    const float* x    = (const float*)d_in[0];
    const void*  idxp = d_in[1];
    const float* W    = (const float*)d_in[2];
    const float* bias = (const float*)d_in[3];
    for (int k = 0; k < n_in; ++k) {
        long long sz = in_sizes[k];
        if (sz == (long long)NUM_Q * SIZE_IN * SIZE_OUT) W    = (const float*)d_in[k];
        else if (sz == SIZE_OUT)                         bias = (const float*)d_in[k];
    }
    float* out = (float*)d_out;

    prep_kernel<<<1, THREADS>>>(idxp, bias, out);

    dim3 grid(J_BLOCKS, I_BLOCKS);  // (2, 256) = 512 CTAs
    indexed_gemv_kernel<<<grid, THREADS>>>(x, W, out);
}